// round 13
// baseline (speedup 1.0000x reference)
#include <cuda_runtime.h>
#include <cuda_fp16.h>
#include <cstdint>
#include <math.h>

// Problem constants
#define BB 2
#define SS 2048
#define DD 256
#define HH 8
#define DK 32
#define DV 32
#define DFF 512
#define NLAYER 2
#define MTOT (BB*SS)          // 4096
#define QKV3 (3*DD)           // 768

#define LOG2E 1.4426950408889634f
#define MV2L (-1e-30f * LOG2E)

// ---------------------------------------------------------------------------
// helpers
// ---------------------------------------------------------------------------
__device__ __forceinline__ uint32_t smem_u32(const void* p) {
    uint32_t a;
    asm("{ .reg .u64 tmp; cvta.to.shared.u64 tmp, %1; cvt.u32.u64 %0, tmp; }"
        : "=r"(a) : "l"(p));
    return a;
}

__device__ __forceinline__ void ldmatrix_x4(uint32_t& a0, uint32_t& a1,
                                            uint32_t& a2, uint32_t& a3,
                                            uint32_t addr) {
    asm volatile("ldmatrix.sync.aligned.m8n8.x4.shared.b16 {%0,%1,%2,%3}, [%4];"
                 : "=r"(a0), "=r"(a1), "=r"(a2), "=r"(a3) : "r"(addr));
}

__device__ __forceinline__ void ldmatrix_x4_trans(uint32_t& a0, uint32_t& a1,
                                                  uint32_t& a2, uint32_t& a3,
                                                  uint32_t addr) {
    asm volatile("ldmatrix.sync.aligned.m8n8.x4.trans.shared.b16 {%0,%1,%2,%3}, [%4];"
                 : "=r"(a0), "=r"(a1), "=r"(a2), "=r"(a3) : "r"(addr));
}

// scalar-argument form: fragments must be register operands, never pointers
__device__ __forceinline__ void mma_16816(float* c, uint32_t a0, uint32_t a1,
                                          uint32_t a2, uint32_t a3,
                                          uint32_t b0, uint32_t b1) {
    asm volatile(
        "mma.sync.aligned.m16n8k16.row.col.f32.f16.f16.f32 "
        "{%0,%1,%2,%3}, {%4,%5,%6,%7}, {%8,%9}, {%0,%1,%2,%3};"
        : "+f"(c[0]), "+f"(c[1]), "+f"(c[2]), "+f"(c[3])
        : "r"(a0), "r"(a1), "r"(a2), "r"(a3), "r"(b0), "r"(b1));
}

__device__ __forceinline__ float ex2f(float x) {
    float r;
    asm("ex2.approx.f32 %0, %1;" : "=f"(r) : "f"(x));
    return r;
}

__device__ __forceinline__ uint32_t pack_h2(float lo, float hi) {
    __half2 v = __floats2half2_rn(lo, hi);
    return *(uint32_t*)&v;
}

__device__ __forceinline__ void cp16(uint32_t dst, const void* src) {
    asm volatile("cp.async.cg.shared.global [%0], [%1], 16;" :: "r"(dst), "l"(src));
}
#define CP_COMMIT() asm volatile("cp.async.commit_group;" ::: "memory")
#define CP_WAIT(N)  asm volatile("cp.async.wait_group %0;" :: "n"(N) : "memory")

// ---------------------------------------------------------------------------
// Scratch (static device globals; no allocation)
// ---------------------------------------------------------------------------
__device__ float g_x[MTOT*DD];
__device__ float g_mones[BB*SS/64];     // per-64-key-chunk all-ones flags
__device__ __half g_xhi[MTOT*DD], g_xlo[MTOT*DD];
__device__ __half g_qkvhi[MTOT*QKV3], g_qkvlo[MTOT*QKV3];
__device__ __half g_ohi[MTOT*DD], g_olo[MTOT*DD];
__device__ __half g_hhi[MTOT*DFF], g_hlo[MTOT*DFF];
__device__ __half g_wqkvhi[NLAYER*QKV3*DD], g_wqkvlo[NLAYER*QKV3*DD];
__device__ __half g_wohi[NLAYER*DD*DD],   g_wolo[NLAYER*DD*DD];
__device__ __half g_w1hi[NLAYER*DFF*DD],  g_w1lo[NLAYER*DFF*DD];
__device__ __half g_w2hi[NLAYER*DD*DFF],  g_w2lo[NLAYER*DD*DFF];

__device__ __forceinline__ void split_store(float v, __half* hi, __half* lo,
                                            size_t idx) {
    __half h = __float2half_rn(v);
    hi[idx] = h;
    lo[idx] = __float2half_rn(v - __half2float(h));
}

__device__ __forceinline__ void split_store2(float v0, float v1, __half* hi,
                                             __half* lo, size_t idx) {
    __half h0 = __float2half_rn(v0), h1 = __float2half_rn(v1);
    *(__half2*)&hi[idx] = __halves2half2(h0, h1);
    *(__half2*)&lo[idx] = __halves2half2(
        __float2half_rn(v0 - __half2float(h0)),
        __float2half_rn(v1 - __half2float(h1)));
}

// ---------------------------------------------------------------------------
// Unified prep: input copy+split, QKV pack, 3x transpose packs, mask flags
// grid = 4096 + 1536 + 128 + 256 + 256 + 1 = 6273
// ---------------------------------------------------------------------------
__global__ void prep_kernel(const float* __restrict__ x,
                            const float* __restrict__ mask,
                            const float* __restrict__ Wq,
                            const float* __restrict__ Wk,
                            const float* __restrict__ Wv,
                            const float* __restrict__ Wo,
                            const float* __restrict__ W1,
                            const float* __restrict__ W2) {
    __shared__ float tile[32][33];
    int bid = blockIdx.x;
    int t = threadIdx.x;

    if (bid == 6272) {                      // mask all-ones flags (64 chunks)
        if (t < BB * SS / 64) {
            const float* mp = mask + t * 64;
            float f = 1.0f;
            for (int u = 0; u < 64; u++)
                if (mp[u] != 1.0f) f = 0.0f;
            g_mones[t] = f;
        }
        return;
    }
    if (bid < 4096) {                       // input copy + split
        size_t i = (size_t)bid * 256 + t;
        float v = x[i];
        g_x[i] = v;
        split_store(v, g_xhi, g_xlo, i);
        return;
    }
    bid -= 4096;
    if (bid < NLAYER * 768) {               // QKV pack
        int layer = bid / 768;
        int idx = (bid % 768) * 256 + t;    // n*256 + d
        int n = idx >> 8, d = idx & 255;
        int sel = n >> 8;
        int r = n & 255;
        int h = r >> 5, kk = r & 31;
        const float* W = (sel == 0) ? Wq : (sel == 1) ? Wk : Wv;
        float v = W[(size_t)layer * HH * DD * DK + (h * DD + d) * DK + kk];
        split_store(v, g_wqkvhi, g_wqkvlo, (size_t)layer * QKV3 * DD + idx);
        return;
    }
    bid -= NLAYER * 768;

    const float* W; __half *hi, *lo; int KK, NN, layer, tileid;
    if (bid < 128)        { layer = bid >> 6;  tileid = bid & 63;
                            W = Wo; hi = g_wohi; lo = g_wolo; KK = DD;  NN = DD;  }
    else if (bid < 384)   { bid -= 128; layer = bid >> 7; tileid = bid & 127;
                            W = W1; hi = g_w1hi; lo = g_w1lo; KK = DD;  NN = DFF; }
    else                  { bid -= 384; layer = bid >> 7; tileid = bid & 127;
                            W = W2; hi = g_w2hi; lo = g_w2lo; KK = DFF; NN = DD;  }
    W  += (size_t)layer * KK * NN;
    hi += (size_t)layer * KK * NN;
    lo += (size_t)layer * KK * NN;
    int ktiles = KK >> 5;
    int k0 = (tileid % ktiles) * 32, n0 = (tileid / ktiles) * 32;

    int tx = t & 31, ty = t >> 5;
    #pragma unroll
    for (int l = 0; l < 4; l++) {
        int k = ty + l * 8;
        tile[k][tx] = W[(size_t)(k0 + k) * NN + n0 + tx];
    }
    __syncthreads();
    #pragma unroll
    for (int l = 0; l < 4; l++) {
        int n = ty + l * 8;
        split_store(tile[tx][n], hi, lo, (size_t)(n0 + n) * KK + k0 + tx);
    }
}

// ---------------------------------------------------------------------------
// HMMA fp16-split GEMM (CTA 128x64, BK=32, 8 warps 4x2), cp.async 2-stage.
// Dedup: load ah/al/bh/bl fragments once per k-step, 3 products from regs.
// ---------------------------------------------------------------------------
#define ASTR 40
#define G_A_HI 0
#define G_A_LO 10240
#define G_B_HI 20480
#define G_B_LO 25600
#define G_STG  30720
#define G_SMEM (2*G_STG)   // 61440

template<bool BIAS, bool RELU, bool SCALEQ>
__global__ void __launch_bounds__(256)
hmma_gemm(const __half* __restrict__ Ahi, const __half* __restrict__ Alo,
          const __half* __restrict__ Bhi, const __half* __restrict__ Blo,
          const float* __restrict__ bias,
          __half* __restrict__ Chi, __half* __restrict__ Clo,
          int M, int N, int K) {
    extern __shared__ char smem[];
    uint32_t sb = smem_u32(smem);

    int t = threadIdx.x, wid = t >> 5, lane = t & 31;
    int warp_m = wid & 3;
    int warp_n = wid >> 2;
    int row0 = blockIdx.y * 128, col0 = blockIdx.x * 64;

    float acc[2][4][4];
    #pragma unroll
    for (int mt = 0; mt < 2; mt++)
        #pragma unroll
        for (int nt = 0; nt < 4; nt++)
            #pragma unroll
            for (int e = 0; e < 4; e++) acc[mt][nt][e] = 0.0f;

    int a_off  = (warp_m * 32 + (lane & 15)) * ASTR + (lane >> 4) * 8;
    int b_off4 = (warp_n * 32 + (lane & 7) + ((lane >> 4) << 3)) * ASTR
               + (((lane >> 3) & 1) << 3);

    auto load_stage = [&](int s, int kc) {
        uint32_t ub = sb + s * G_STG;
        #pragma unroll
        for (int l = 0; l < 2; l++) {
            int idx = t + l * 256;
            int r = idx >> 2, c4 = idx & 3;
            size_t gsrc = (size_t)(row0 + r) * K + kc + c4 * 8;
            cp16(ub + G_A_HI + r * 80 + c4 * 16, Ahi + gsrc);
            cp16(ub + G_A_LO + r * 80 + c4 * 16, Alo + gsrc);
        }
        {
            int r = t >> 2, c4 = t & 3;
            size_t gsrc = (size_t)(col0 + r) * K + kc + c4 * 8;
            cp16(ub + G_B_HI + r * 80 + c4 * 16, Bhi + gsrc);
            cp16(ub + G_B_LO + r * 80 + c4 * 16, Blo + gsrc);
        }
    };

    int nk = K >> 5;
    load_stage(0, 0);
    CP_COMMIT();

    for (int i = 0; i < nk; i++) {
        if (i + 1 < nk) { load_stage((i + 1) & 1, (i + 1) * 32); CP_COMMIT(); CP_WAIT(1); }
        else            { CP_WAIT(0); }
        __syncthreads();

        uint32_t stg = sb + (i & 1) * G_STG;
        #pragma unroll
        for (int kk = 0; kk < 32; kk += 16) {
            uint32_t ah[2][4], al[2][4];
            #pragma unroll
            for (int mt = 0; mt < 2; mt++) {
                uint32_t ao = (uint32_t)(a_off + mt * 16 * ASTR + kk) * 2;
                ldmatrix_x4(ah[mt][0], ah[mt][1], ah[mt][2], ah[mt][3],
                            stg + G_A_HI + ao);
                ldmatrix_x4(al[mt][0], al[mt][1], al[mt][2], al[mt][3],
                            stg + G_A_LO + ao);
            }
            uint32_t bh[4][2], bl[4][2];
            #pragma unroll
            for (int p = 0; p < 2; p++) {
                uint32_t bo = (uint32_t)(b_off4 + p * 16 * ASTR + kk) * 2;
                ldmatrix_x4(bh[2*p][0], bh[2*p][1], bh[2*p+1][0], bh[2*p+1][1],
                            stg + G_B_HI + bo);
                ldmatrix_x4(bl[2*p][0], bl[2*p][1], bl[2*p+1][0], bl[2*p+1][1],
                            stg + G_B_LO + bo);
            }
            #pragma unroll
            for (int mt = 0; mt < 2; mt++)
                #pragma unroll
                for (int nt = 0; nt < 4; nt++) {
                    mma_16816(acc[mt][nt], ah[mt][0], ah[mt][1], ah[mt][2],
                              ah[mt][3], bh[nt][0], bh[nt][1]);
                    mma_16816(acc[mt][nt], ah[mt][0], ah[mt][1], ah[mt][2],
                              ah[mt][3], bl[nt][0], bl[nt][1]);
                    mma_16816(acc[mt][nt], al[mt][0], al[mt][1], al[mt][2],
                              al[mt][3], bh[nt][0], bh[nt][1]);
                }
        }
        __syncthreads();
    }

    #pragma unroll
    for (int mt = 0; mt < 2; mt++) {
        int r_lo = row0 + warp_m * 32 + mt * 16 + (lane >> 2);
        #pragma unroll
        for (int nt = 0; nt < 4; nt++) {
            int c = col0 + warp_n * 32 + nt * 8 + (lane & 3) * 2;
            #pragma unroll
            for (int half = 0; half < 2; half++) {
                int r = r_lo + half * 8;
                size_t rb = (size_t)r * N;
                float v0 = acc[mt][nt][half * 2 + 0];
                float v1 = acc[mt][nt][half * 2 + 1];
                if (BIAS) { v0 += bias[c]; v1 += bias[c + 1]; }
                if (RELU) { v0 = fmaxf(v0, 0.0f); v1 = fmaxf(v1, 0.0f); }
                if (SCALEQ) { if (c < DD) { v0 *= LOG2E; v1 *= LOG2E; } }
                split_store2(v0, v1, Chi, Clo, rb + c);
            }
        }
    }
}

// ---------------------------------------------------------------------------
// GEMM + residual + LayerNorm fused. Tile 16x256 (grid = 256 CTAs, >= SMs),
// 8 warps each owning 32 output cols; low regs -> 2 CTAs/SM. 2-stage.
// ---------------------------------------------------------------------------
#define LG_A_HI 0
#define LG_A_LO 1280
#define LG_B_HI 2560
#define LG_B_LO 23040
#define LG_STG  43520
#define LG_SMEM (2*LG_STG)   // 87040 (epilogue 16KB fp32 buffer aliases stage 0)

template<bool BIAS, bool SPLITOUT>
__global__ void __launch_bounds__(256)
ln_gemm(const __half* __restrict__ Ahi, const __half* __restrict__ Alo,
        const __half* __restrict__ Bhi, const __half* __restrict__ Blo,
        const float* __restrict__ bias, const float* __restrict__ resp,
        float* __restrict__ xout, __half* __restrict__ Xhi,
        __half* __restrict__ Xlo, const float* __restrict__ gamma,
        const float* __restrict__ beta, int gi, int K) {
    extern __shared__ char smem[];
    uint32_t sb = smem_u32(smem);

    int t = threadIdx.x, wid = t >> 5, lane = t & 31;
    int row0 = blockIdx.x * 16;

    float acc[4][4];
    #pragma unroll
    for (int nt = 0; nt < 4; nt++)
        #pragma unroll
        for (int e = 0; e < 4; e++) acc[nt][e] = 0.0f;

    int a_off   = (lane & 15) * ASTR + (lane >> 4) * 8;
    int b_lane4 = (wid * 32 + (lane & 7) + ((lane >> 4) << 3)) * ASTR
                + (((lane >> 3) & 1) << 3);

    auto load_stage = [&](int s, int kc) {
        uint32_t ub = sb + s * LG_STG;
        if (t < 128) {   // A: 16 rows x 32 halves x hi/lo = 128 cp16
            int r = t >> 3, which = (t >> 2) & 1, c4 = t & 3;
            size_t gsrc = (size_t)(row0 + r) * K + kc + c4 * 8;
            cp16(ub + (which ? LG_A_LO : LG_A_HI) + r * 80 + c4 * 16,
                 (which ? Alo : Ahi) + gsrc);
        }
        #pragma unroll
        for (int l = 0; l < 8; l++) {   // B: 256 rows x 32 x hi/lo = 2048 cp16
            int idx = t + l * 256;
            int r = idx >> 3, which = (idx >> 2) & 1, c4 = idx & 3;
            size_t gsrc = (size_t)r * K + kc + c4 * 8;
            cp16(ub + (which ? LG_B_LO : LG_B_HI) + r * 80 + c4 * 16,
                 (which ? Blo : Bhi) + gsrc);
        }
    };

    int nk = K >> 5;
    load_stage(0, 0);
    CP_COMMIT();

    for (int i = 0; i < nk; i++) {
        if (i + 1 < nk) { load_stage((i + 1) & 1, (i + 1) * 32); CP_COMMIT(); CP_WAIT(1); }
        else            { CP_WAIT(0); }
        __syncthreads();

        uint32_t stg = sb + (i & 1) * LG_STG;
        #pragma unroll
        for (int s = 0; s < 3; s++) {
            uint32_t baseA = stg + ((s == 2) ? LG_A_LO : LG_A_HI);
            uint32_t baseB = stg + ((s == 1) ? LG_B_LO : LG_B_HI);
            #pragma unroll
            for (int kk = 0; kk < 32; kk += 16) {
                uint32_t a0, a1, a2, a3;
                ldmatrix_x4(a0, a1, a2, a3, baseA + (uint32_t)(a_off + kk) * 2);
                #pragma unroll
                for (int p = 0; p < 2; p++) {
                    uint32_t b0, b1, b2, b3;
                    ldmatrix_x4(b0, b1, b2, b3,
                        baseB + (uint32_t)(b_lane4 + p * 16 * ASTR + kk) * 2);
                    mma_16816(acc[2*p],   a0, a1, a2, a3, b0, b1);
                    mma_16816(acc[2*p+1], a0, a1, a2, a3, b2, b3);
                }
            }
        }
        __syncthreads();
    }

    // phase 1: bias + residual into fp32 smem rows (16 x 256)
    float* fb = (float*)smem;
    #pragma unroll
    for (int nt = 0; nt < 4; nt++) {
        int col = wid * 32 + nt * 8 + (lane & 3) * 2;
        int rl  = lane >> 2;
        #pragma unroll
        for (int half = 0; half < 2; half++) {
            int r = rl + half * 8;
            size_t grb = (size_t)(row0 + r) * DD;
            float v0 = acc[nt][half * 2 + 0];
            float v1 = acc[nt][half * 2 + 1];
            if (BIAS) { v0 += bias[col]; v1 += bias[col + 1]; }
            v0 += resp[grb + col];
            v1 += resp[grb + col + 1];
            fb[r * DD + col] = v0;
            fb[r * DD + col + 1] = v1;
        }
    }
    __syncthreads();

    // phase 2: warp-per-row LayerNorm (each warp: 2 rows)
    float g = gamma[gi], bb = beta[gi];
    #pragma unroll
    for (int j = 0; j < 2; j++) {
        int r = wid * 2 + j;
        const float4* rp = (const float4*)(fb + r * DD);
        float4 v0 = rp[lane * 2], v1 = rp[lane * 2 + 1];

        float sum = v0.x + v0.y + v0.z + v0.w + v1.x + v1.y + v1.z + v1.w;
        #pragma unroll
        for (int off = 16; off > 0; off >>= 1)
            sum += __shfl_xor_sync(0xffffffffu, sum, off);
        float mean = sum * (1.0f / DD);

        float d0 = v0.x - mean, d1 = v0.y - mean, d2 = v0.z - mean, d3 = v0.w - mean;
        float d4 = v1.x - mean, d5 = v1.y - mean, d6 = v1.z - mean, d7 = v1.w - mean;
        float s2 = d0*d0 + d1*d1 + d2*d2 + d3*d3 + d4*d4 + d5*d5 + d6*d6 + d7*d7;
        #pragma unroll
        for (int off = 16; off > 0; off >>= 1)
            s2 += __shfl_xor_sync(0xffffffffu, s2, off);
        float rstd = rsqrtf(s2 * (1.0f / DD) + 1e-14f) * g;

        float o[8] = { d0*rstd + bb, d1*rstd + bb, d2*rstd + bb, d3*rstd + bb,
                       d4*rstd + bb, d5*rstd + bb, d6*rstd + bb, d7*rstd + bb };
        size_t gbase = (size_t)(row0 + r) * DD + lane * 8;
        *(float4*)(xout + gbase)     = make_float4(o[0], o[1], o[2], o[3]);
        *(float4*)(xout + gbase + 4) = make_float4(o[4], o[5], o[6], o[7]);
        if (SPLITOUT) {
            #pragma unroll
            for (int p = 0; p < 4; p++)
                split_store2(o[2*p], o[2*p+1], Xhi, Xlo, gbase + 2*p);
        }
    }
}

// ---------------------------------------------------------------------------
// HMMA flash attention: fp16 splits, cp.async 2-stage KV, 4 warps.
// QK dedup (K frags once); mask fast path via per-chunk all-ones flag.
// ---------------------------------------------------------------------------
#define ATT_Q_HI 0
#define ATT_Q_LO 10240
#define ATT_KV0  20480            // + stage*20480 + {Khi:0,Klo:5120,Vhi:10240,Vlo:15360}
#define ATT_KSTG 20480
#define ATT_M0   61440            // + stage*512 ; mask 64 floats, flag at +256
#define ATT_SMEM 62464

__global__ void __launch_bounds__(128) attention_hmma(const float* __restrict__ mask) {
    extern __shared__ char smem[];
    uint32_t sb = smem_u32(smem);

    int b = blockIdx.y >> 3, h = blockIdx.y & 7;
    int t = threadIdx.x, warp = t >> 5, lane = t & 31;
    int row0 = blockIdx.x * 128;

    auto load_kv = [&](int s, int t0) {
        uint32_t ub = sb + ATT_KV0 + s * ATT_KSTG;
        #pragma unroll
        for (int l = 0; l < 8; l++) {
            int idx = t + l * 128;
            int r = idx >> 4, which = (idx >> 2) & 3, c4 = idx & 3;
            const __half* src = (which & 1) ? g_qkvlo : g_qkvhi;
            int coff = ((which < 2) ? DD : 2 * DD) + h * DK + c4 * 8;
            cp16(ub + which * 5120 + r * 80 + c4 * 16,
                 src + (size_t)(b * SS + t0 + r) * QKV3 + coff);
        }
        if (t < 64)
            *(float*)(smem + ATT_M0 + s * 512 + t * 4) = mask[b * SS + t0 + t];
        if (t == 64)
            *(float*)(smem + ATT_M0 + s * 512 + 256) = g_mones[(b * SS + t0) >> 6];
    };

    load_kv(0, 0);
    CP_COMMIT();

    {
        size_t qbase = (size_t)(b * SS + row0) * QKV3 + h * DK;
        #pragma unroll
        for (int l = 0; l < 8; l++) {
            int idx = t + l * 128;
            int r = idx >> 3, which = (idx >> 2) & 1, c4 = idx & 3;
            const __half* src = which ? g_qkvlo : g_qkvhi;
            *(uint4*)(smem + (which ? ATT_Q_LO : ATT_Q_HI) + r * 80 + c4 * 16) =
                *(const uint4*)&src[qbase + (size_t)r * QKV3 + c4 * 8];
        }
    }
    __syncthreads();

    uint32_t qf[2][2][2][4];   // [hi/lo][mt][kstep][4]
    {
        int a_off = (warp * 32 + (lane & 15)) * ASTR + (lane >> 4) * 8;
        #pragma unroll
        for (int w2 = 0; w2 < 2; w2++) {
            uint32_t base = sb + (w2 ? ATT_Q_LO : ATT_Q_HI);
            #pragma unroll
            for (int mt = 0; mt < 2; mt++)
                #pragma unroll
                for (int ks = 0; ks < 2; ks++)
                    ldmatrix_x4(qf[w2][mt][ks][0], qf[w2][mt][ks][1],
                                qf[w2][mt][ks][2], qf[w2][mt][ks][3],
                                base + (uint32_t)(a_off + mt * 16 * ASTR + ks * 16) * 2);
        }
    }

    float m_run[2][2], l_run[2][2], oacc[2][4][4];
    #pragma unroll
    for (int mt = 0; mt < 2; mt++) {
        #pragma unroll
        for (int hf = 0; hf < 2; hf++) { m_run[mt][hf] = -1e30f; l_run[mt][hf] = 0.f; }
        #pragma unroll
        for (int nt = 0; nt < 4; nt++)
            #pragma unroll
            for (int e = 0; e < 4; e++) oacc[mt][nt][e] = 0.f;
    }

    const int ntiles = SS / 64;
    for (int i = 0; i < ntiles; i++) {
        if (i + 1 < ntiles) { load_kv((i + 1) & 1, (i + 1) * 64); CP_COMMIT(); CP_WAIT(1); }
        else                { CP_WAIT(0); }
        __syncthreads();

        uint32_t kvstg = sb + ATT_KV0 + (i & 1) * ATT_KSTG;
        const float* sM = (const float*)(smem + ATT_M0 + (i & 1) * 512);
        float ones = *(const float*)(smem + ATT_M0 + (i & 1) * 512 + 256);

        // S = Q K^T: K fragments loaded once (hi+lo), 3 products from regs
        float sc[2][8][4];
        #pragma unroll
        for (int mt = 0; mt < 2; mt++)
            #pragma unroll
            for (int nt = 0; nt < 8; nt++)
                #pragma unroll
                for (int e = 0; e < 4; e++) sc[mt][nt][e] = 0.f;
        {
            int b_off4 = ((lane & 7) + ((lane >> 4) << 3)) * ASTR
                       + (((lane >> 3) & 1) << 3);
            #pragma unroll
            for (int ks = 0; ks < 2; ks++)
                #pragma unroll
                for (int p = 0; p < 4; p++) {
                    uint32_t ko = (uint32_t)(b_off4 + p * 16 * ASTR + ks * 16) * 2;
                    uint32_t k0, k1, k2, k3, l0, l1, l2, l3;
                    ldmatrix_x4(k0, k1, k2, k3, kvstg + ko);
                    ldmatrix_x4(l0, l1, l2, l3, kvstg + 5120 + ko);
                    #pragma unroll
                    for (int mt = 0; mt < 2; mt++) {
                        mma_16816(sc[mt][2*p],   qf[0][mt][ks][0], qf[0][mt][ks][1],
                                  qf[0][mt][ks][2], qf[0][mt][ks][3], k0, k1);
                        mma_16816(sc[mt][2*p+1], qf[0][mt][ks][0], qf[0][mt][ks][1],
                                  qf[0][mt][ks][2], qf[0][mt][ks][3], k2, k3);
                        mma_16816(sc[mt][2*p],   qf[0][mt][ks][0], qf[0][mt][ks][1],
                                  qf[0][mt][ks][2], qf[0][mt][ks][3], l0, l1);
                        mma_16816(sc[mt][2*p+1], qf[0][mt][ks][0], qf[0][mt][ks][1],
                                  qf[0][mt][ks][2], qf[0][mt][ks][3], l2, l3);
                        mma_16816(sc[mt][2*p],   qf[1][mt][ks][0], qf[1][mt][ks][1],
                                  qf[1][mt][ks][2], qf[1][mt][ks][3], k0, k1);
                        mma_16816(sc[mt][2*p+1], qf[1][mt][ks][0], qf[1][mt][ks][1],
                                  qf[1][mt][ks][2], qf[1][mt][ks][3], k2, k3);
                    }
                }
        }

        // masking: skipped entirely when chunk is all-ones (bit-exact: m=1 ->
        // fmaf(1,A,0)=A). Otherwise apply the reference formula.
        if (ones == 0.0f) {
            #pragma unroll
            for (int nt = 0; nt < 8; nt++) {
                int c0 = nt * 8 + (lane & 3) * 2;
                float mvA = sM[c0], mvB = sM[c0 + 1];
                float cA = (1.f - mvA) * MV2L, cB = (1.f - mvB) * MV2L;
                #pragma unroll
                for (int mt = 0; mt < 2; mt++) {
                    sc[mt][nt][0] = fmaf(mvA, sc[mt][nt][0], cA);
                    sc[mt][nt][1] = fmaf(mvB, sc[mt][nt][1], cB);
                    sc[mt][nt][2] = fmaf(mvA, sc[mt][nt][2], cA);
                    sc[mt][nt][3] = fmaf(mvB, sc[mt][nt][3], cB);
                }
            }
        }

        float tmax[2][2] = {{-1e30f, -1e30f}, {-1e30f, -1e30f}};
        #pragma unroll
        for (int nt = 0; nt < 8; nt++)
            #pragma unroll
            for (int mt = 0; mt < 2; mt++) {
                tmax[mt][0] = fmaxf(tmax[mt][0], fmaxf(sc[mt][nt][0], sc[mt][nt][1]));
                tmax[mt][1] = fmaxf(tmax[mt][1], fmaxf(sc[mt][nt][2], sc[mt][nt][3]));
            }
        float corr[2][2];
        #pragma unroll
        for (int mt = 0; mt < 2; mt++)
            #pragma unroll
            for (int hf = 0; hf < 2; hf++) {
                float v = tmax[mt][hf];
                v = fmaxf(v, __shfl_xor_sync(0xffffffffu, v, 1));
                v = fmaxf(v, __shfl_xor_sync(0xffffffffu, v, 2));
                float mn = fmaxf(m_run[mt][hf], v);
                corr[mt][hf] = ex2f(m_run[mt][hf] - mn);
                m_run[mt][hf] = mn;
                l_run[mt][hf] *= corr[mt][hf];
            }
        #pragma unroll
        for (int mt = 0; mt < 2; mt++)
            #pragma unroll
            for (int nt = 0; nt < 4; nt++)
                #pragma unroll
                for (int e = 0; e < 4; e++)
                    oacc[mt][nt][e] *= corr[mt][e >> 1];

        uint32_t pf[2][4][4];
        #pragma unroll
        for (int mt = 0; mt < 2; mt++)
            #pragma unroll
            for (int nt = 0; nt < 8; nt++) {
                float p0 = ex2f(sc[mt][nt][0] - m_run[mt][0]);
                float p1 = ex2f(sc[mt][nt][1] - m_run[mt][0]);
                float p2 = ex2f(sc[mt][nt][2] - m_run[mt][1]);
                float p3 = ex2f(sc[mt][nt][3] - m_run[mt][1]);
                l_run[mt][0] += p0 + p1;
                l_run[mt][1] += p2 + p3;
                int kb = nt >> 1, hi2 = (nt & 1) * 2;
                pf[mt][kb][hi2 + 0] = pack_h2(p0, p1);
                pf[mt][kb][hi2 + 1] = pack_h2(p2, p3);
            }

        // O += P @ V (Vhi pass + Vlo pass), trans x4 loads
        #pragma unroll
        for (int s = 0; s < 2; s++) {
            uint32_t vbase = kvstg + (2 + s) * 5120;
            #pragma unroll
            for (int kb = 0; kb < 4; kb++) {
                uint32_t vrow = vbase +
                    (uint32_t)((kb * 16 + (lane & 15)) * ASTR + ((lane >> 4) << 3)) * 2;
                #pragma unroll
                for (int p = 0; p < 2; p++) {
                    uint32_t b0, b1, b2, b3;
                    ldmatrix_x4_trans(b0, b1, b2, b3, vrow + (uint32_t)(p * 16) * 2);
                    mma_16816(oacc[0][2*p],   pf[0][kb][0], pf[0][kb][1],
                              pf[0][kb][2], pf[0][kb][3], b0, b1);
                    mma_16816(oacc[0][2*p+1], pf[0][kb][0], pf[0][kb][1],
                              pf[0][kb][2], pf[0][kb][3], b2, b3);
                    mma_16816(oacc[1][2*p],   pf[1][kb][0], pf[1][kb][1],
                              pf[1][kb][2], pf[1][kb][3], b0, b1);
                    mma_16816(oacc[1][2*p+1], pf[1][kb][0], pf[1][kb][1],
                              pf[1][kb][2], pf[1][kb][3], b2, b3);
                }
            }
        }
        __syncthreads();
    }

    #pragma unroll
    for (int mt = 0; mt < 2; mt++)
        #pragma unroll
        for (int hf = 0; hf < 2; hf++) {
            float v = l_run[mt][hf];
            v += __shfl_xor_sync(0xffffffffu, v, 1);
            v += __shfl_xor_sync(0xffffffffu, v, 2);
            l_run[mt][hf] = 1.0f / v;
        }
    #pragma unroll
    for (int mt = 0; mt < 2; mt++)
        #pragma unroll
        for (int hf = 0; hf < 2; hf++) {
            int row = row0 + warp * 32 + mt * 16 + (lane >> 2) + hf * 8;
            size_t obase = (size_t)(b * SS + row) * DD + h * DV;
            float inv = l_run[mt][hf];
            #pragma unroll
            for (int nt = 0; nt < 4; nt++) {
                int col = nt * 8 + (lane & 3) * 2;
                split_store2(oacc[mt][nt][hf * 2 + 0] * inv,
                             oacc[mt][nt][hf * 2 + 1] * inv,
                             g_ohi, g_olo, obase + col);
            }
        }
}

// ---------------------------------------------------------------------------
// launch
// ---------------------------------------------------------------------------
extern "C" void kernel_launch(void* const* d_in, const int* in_sizes, int n_in,
                              void* d_out, int out_size) {
    const float* x     = (const float*)d_in[0];
    const float* mask  = (const float*)d_in[1];
    const float* Wq    = (const float*)d_in[2];
    const float* Wk    = (const float*)d_in[3];
    const float* Wv    = (const float*)d_in[4];
    const float* Wo    = (const float*)d_in[5];
    const float* W1    = (const float*)d_in[6];
    const float* b1    = (const float*)d_in[7];
    const float* W2    = (const float*)d_in[8];
    const float* b2    = (const float*)d_in[9];
    const float* gamma = (const float*)d_in[10];
    const float* beta  = (const float*)d_in[11];
    float* out = (float*)d_out;
    (void)in_sizes; (void)n_in; (void)out_size;

    float *p_x;
    __half *p_xhi, *p_xlo, *p_ohi, *p_olo, *p_hhi, *p_hlo, *p_qkvhi, *p_qkvlo;
    __half *p_wqkvhi, *p_wqkvlo, *p_wohi, *p_wolo, *p_w1hi, *p_w1lo, *p_w2hi, *p_w2lo;
    cudaGetSymbolAddress((void**)&p_x, g_x);
    cudaGetSymbolAddress((void**)&p_xhi, g_xhi);
    cudaGetSymbolAddress((void**)&p_xlo, g_xlo);
    cudaGetSymbolAddress((void**)&p_qkvhi, g_qkvhi);
    cudaGetSymbolAddress((void**)&p_qkvlo, g_qkvlo);
    cudaGetSymbolAddress((void**)&p_ohi, g_ohi);
    cudaGetSymbolAddress((void**)&p_olo, g_olo);
    cudaGetSymbolAddress((void**)&p_hhi, g_hhi);
    cudaGetSymbolAddress((void**)&p_hlo, g_hlo);
    cudaGetSymbolAddress((void**)&p_wqkvhi, g_wqkvhi);
    cudaGetSymbolAddress((void**)&p_wqkvlo, g_wqkvlo);
    cudaGetSymbolAddress((void**)&p_wohi, g_wohi);
    cudaGetSymbolAddress((void**)&p_wolo, g_wolo);
    cudaGetSymbolAddress((void**)&p_w1hi, g_w1hi);
    cudaGetSymbolAddress((void**)&p_w1lo, g_w1lo);
    cudaGetSymbolAddress((void**)&p_w2hi, g_w2hi);
    cudaGetSymbolAddress((void**)&p_w2lo, g_w2lo);

    cudaFuncSetAttribute(hmma_gemm<false,false,true>,
                         cudaFuncAttributeMaxDynamicSharedMemorySize, G_SMEM);
    cudaFuncSetAttribute(hmma_gemm<true,true,false>,
                         cudaFuncAttributeMaxDynamicSharedMemorySize, G_SMEM);
    cudaFuncSetAttribute(ln_gemm<false,true>,
                         cudaFuncAttributeMaxDynamicSharedMemorySize, LG_SMEM);
    cudaFuncSetAttribute(ln_gemm<true,true>,
                         cudaFuncAttributeMaxDynamicSharedMemorySize, LG_SMEM);
    cudaFuncSetAttribute(ln_gemm<true,false>,
                         cudaFuncAttributeMaxDynamicSharedMemorySize, LG_SMEM);
    cudaFuncSetAttribute(attention_hmma,
                         cudaFuncAttributeMaxDynamicSharedMemorySize, ATT_SMEM);

    // one prep launch: copy + split + all weight packs + mask flags
    prep_kernel<<<4096 + NLAYER*768 + 128 + 256 + 256 + 1, 256>>>(
        x, mask, Wq, Wk, Wv, Wo, W1, W2);

    for (int i = 0; i < NLAYER; i++) {
        // qkv = x @ Wqkv  (split fp16 out; q scaled by log2e)
        hmma_gemm<false,false,true><<<dim3(QKV3/64, MTOT/128), 256, G_SMEM>>>(
            p_xhi, p_xlo,
            p_wqkvhi + (size_t)i * QKV3 * DD, p_wqkvlo + (size_t)i * QKV3 * DD,
            nullptr, p_qkvhi, p_qkvlo, MTOT, QKV3, DD);

        // flash attention -> o split fp16
        attention_hmma<<<dim3(SS/128, BB*HH), 128, ATT_SMEM>>>(mask);

        // x = LN(x + o @ Wo)
        ln_gemm<false,true><<<MTOT/16, 256, LG_SMEM>>>(
            p_ohi, p_olo,
            p_wohi + (size_t)i * DD * DD, p_wolo + (size_t)i * DD * DD,
            nullptr, p_x, p_x, p_xhi, p_xlo, gamma, beta, 2*i, DD);

        // h = relu(x @ W1 + b1) -> split fp16
        hmma_gemm<true,true,false><<<dim3(DFF/64, MTOT/128), 256, G_SMEM>>>(
            p_xhi, p_xlo,
            p_w1hi + (size_t)i * DFF * DD, p_w1lo + (size_t)i * DFF * DD,
            b1 + (size_t)i * DFF, p_hhi, p_hlo, MTOT, DFF, DD);

        // x = LN(x + h @ W2 + b2)  (final layer -> out)
        if (i == NLAYER - 1) {
            ln_gemm<true,false><<<MTOT/16, 256, LG_SMEM>>>(
                p_hhi, p_hlo,
                p_w2hi + (size_t)i * DD * DFF, p_w2lo + (size_t)i * DD * DFF,
                b2 + (size_t)i * DD, p_x, out, nullptr, nullptr,
                gamma, beta, 2*i+1, DFF);
        } else {
            ln_gemm<true,true><<<MTOT/16, 256, LG_SMEM>>>(
                p_hhi, p_hlo,
                p_w2hi + (size_t)i * DD * DFF, p_w2lo + (size_t)i * DD * DFF,
                b2 + (size_t)i * DD, p_x, p_x, p_xhi, p_xlo,
                gamma, beta, 2*i+1, DFF);
        }
    }
}

// round 14
// speedup vs baseline: 1.0651x; 1.0651x over previous
#include <cuda_runtime.h>
#include <cuda_fp16.h>
#include <cstdint>
#include <math.h>

// Problem constants
#define BB 2
#define SS 2048
#define DD 256
#define HH 8
#define DK 32
#define DV 32
#define DFF 512
#define NLAYER 2
#define MTOT (BB*SS)          // 4096
#define QKV3 (3*DD)           // 768

#define LOG2E 1.4426950408889634f
#define MV2L (-1e-30f * LOG2E)

// ---------------------------------------------------------------------------
// helpers
// ---------------------------------------------------------------------------
__device__ __forceinline__ uint32_t smem_u32(const void* p) {
    uint32_t a;
    asm("{ .reg .u64 tmp; cvta.to.shared.u64 tmp, %1; cvt.u32.u64 %0, tmp; }"
        : "=r"(a) : "l"(p));
    return a;
}

__device__ __forceinline__ void ldmatrix_x4(uint32_t& a0, uint32_t& a1,
                                            uint32_t& a2, uint32_t& a3,
                                            uint32_t addr) {
    asm volatile("ldmatrix.sync.aligned.m8n8.x4.shared.b16 {%0,%1,%2,%3}, [%4];"
                 : "=r"(a0), "=r"(a1), "=r"(a2), "=r"(a3) : "r"(addr));
}

__device__ __forceinline__ void ldmatrix_x4_trans(uint32_t& a0, uint32_t& a1,
                                                  uint32_t& a2, uint32_t& a3,
                                                  uint32_t addr) {
    asm volatile("ldmatrix.sync.aligned.m8n8.x4.trans.shared.b16 {%0,%1,%2,%3}, [%4];"
                 : "=r"(a0), "=r"(a1), "=r"(a2), "=r"(a3) : "r"(addr));
}

// scalar-argument form: fragments must be register operands, never pointers
__device__ __forceinline__ void mma_16816(float* c, uint32_t a0, uint32_t a1,
                                          uint32_t a2, uint32_t a3,
                                          uint32_t b0, uint32_t b1) {
    asm volatile(
        "mma.sync.aligned.m16n8k16.row.col.f32.f16.f16.f32 "
        "{%0,%1,%2,%3}, {%4,%5,%6,%7}, {%8,%9}, {%0,%1,%2,%3};"
        : "+f"(c[0]), "+f"(c[1]), "+f"(c[2]), "+f"(c[3])
        : "r"(a0), "r"(a1), "r"(a2), "r"(a3), "r"(b0), "r"(b1));
}

__device__ __forceinline__ float ex2f(float x) {
    float r;
    asm("ex2.approx.f32 %0, %1;" : "=f"(r) : "f"(x));
    return r;
}

__device__ __forceinline__ uint32_t pack_h2(float lo, float hi) {
    __half2 v = __floats2half2_rn(lo, hi);
    return *(uint32_t*)&v;
}

__device__ __forceinline__ void cp16(uint32_t dst, const void* src) {
    asm volatile("cp.async.cg.shared.global [%0], [%1], 16;" :: "r"(dst), "l"(src));
}
#define CP_COMMIT() asm volatile("cp.async.commit_group;" ::: "memory")
#define CP_WAIT(N)  asm volatile("cp.async.wait_group %0;" :: "n"(N) : "memory")

// ---------------------------------------------------------------------------
// Scratch (static device globals; no allocation)
// ---------------------------------------------------------------------------
#define HSZ (BB*HH*SS*DK)     // per-head q/k/v array size (1M halves)
__device__ float g_x[MTOT*DD];
__device__ float g_mones[BB*SS/64];     // per-64-key-chunk all-ones flags
__device__ __half g_xhi[MTOT*DD], g_xlo[MTOT*DD];
__device__ __half g_qhi[HSZ], g_qlo[HSZ];
__device__ __half g_khi[HSZ], g_klo[HSZ];
__device__ __half g_vhi[HSZ], g_vlo[HSZ];
__device__ __half g_ohi[MTOT*DD], g_olo[MTOT*DD];
__device__ __half g_hhi[MTOT*DFF], g_hlo[MTOT*DFF];
__device__ __half g_wqkvhi[NLAYER*QKV3*DD], g_wqkvlo[NLAYER*QKV3*DD];
__device__ __half g_wohi[NLAYER*DD*DD],   g_wolo[NLAYER*DD*DD];
__device__ __half g_w1hi[NLAYER*DFF*DD],  g_w1lo[NLAYER*DFF*DD];
__device__ __half g_w2hi[NLAYER*DD*DFF],  g_w2lo[NLAYER*DD*DFF];

__device__ __forceinline__ void split_store(float v, __half* hi, __half* lo,
                                            size_t idx) {
    __half h = __float2half_rn(v);
    hi[idx] = h;
    lo[idx] = __float2half_rn(v - __half2float(h));
}

__device__ __forceinline__ void split_store2(float v0, float v1, __half* hi,
                                             __half* lo, size_t idx) {
    __half h0 = __float2half_rn(v0), h1 = __float2half_rn(v1);
    *(__half2*)&hi[idx] = __halves2half2(h0, h1);
    *(__half2*)&lo[idx] = __halves2half2(
        __float2half_rn(v0 - __half2float(h0)),
        __float2half_rn(v1 - __half2float(h1)));
}

// ---------------------------------------------------------------------------
// Unified prep: input copy+split, QKV pack, 3x transpose packs, mask flags
// grid = 4096 + 1536 + 128 + 256 + 256 + 1 = 6273
// ---------------------------------------------------------------------------
__global__ void prep_kernel(const float* __restrict__ x,
                            const float* __restrict__ mask,
                            const float* __restrict__ Wq,
                            const float* __restrict__ Wk,
                            const float* __restrict__ Wv,
                            const float* __restrict__ Wo,
                            const float* __restrict__ W1,
                            const float* __restrict__ W2) {
    __shared__ float tile[32][33];
    int bid = blockIdx.x;
    int t = threadIdx.x;

    if (bid == 6272) {                      // mask all-ones flags (64 chunks)
        if (t < BB * SS / 64) {
            const float* mp = mask + t * 64;
            float f = 1.0f;
            for (int u = 0; u < 64; u++)
                if (mp[u] != 1.0f) f = 0.0f;
            g_mones[t] = f;
        }
        return;
    }
    if (bid < 4096) {                       // input copy + split
        size_t i = (size_t)bid * 256 + t;
        float v = x[i];
        g_x[i] = v;
        split_store(v, g_xhi, g_xlo, i);
        return;
    }
    bid -= 4096;
    if (bid < NLAYER * 768) {               // QKV pack
        int layer = bid / 768;
        int idx = (bid % 768) * 256 + t;    // n*256 + d
        int n = idx >> 8, d = idx & 255;
        int sel = n >> 8;
        int r = n & 255;
        int h = r >> 5, kk = r & 31;
        const float* W = (sel == 0) ? Wq : (sel == 1) ? Wk : Wv;
        float v = W[(size_t)layer * HH * DD * DK + (h * DD + d) * DK + kk];
        split_store(v, g_wqkvhi, g_wqkvlo, (size_t)layer * QKV3 * DD + idx);
        return;
    }
    bid -= NLAYER * 768;

    const float* W; __half *hi, *lo; int KK, NN, layer, tileid;
    if (bid < 128)        { layer = bid >> 6;  tileid = bid & 63;
                            W = Wo; hi = g_wohi; lo = g_wolo; KK = DD;  NN = DD;  }
    else if (bid < 384)   { bid -= 128; layer = bid >> 7; tileid = bid & 127;
                            W = W1; hi = g_w1hi; lo = g_w1lo; KK = DD;  NN = DFF; }
    else                  { bid -= 384; layer = bid >> 7; tileid = bid & 127;
                            W = W2; hi = g_w2hi; lo = g_w2lo; KK = DFF; NN = DD;  }
    W  += (size_t)layer * KK * NN;
    hi += (size_t)layer * KK * NN;
    lo += (size_t)layer * KK * NN;
    int ktiles = KK >> 5;
    int k0 = (tileid % ktiles) * 32, n0 = (tileid / ktiles) * 32;

    int tx = t & 31, ty = t >> 5;
    #pragma unroll
    for (int l = 0; l < 4; l++) {
        int k = ty + l * 8;
        tile[k][tx] = W[(size_t)(k0 + k) * NN + n0 + tx];
    }
    __syncthreads();
    #pragma unroll
    for (int l = 0; l < 4; l++) {
        int n = ty + l * 8;
        split_store(tile[tx][n], hi, lo, (size_t)(n0 + n) * KK + k0 + tx);
    }
}

// ---------------------------------------------------------------------------
// HMMA fp16-split GEMM (CTA 128x64, BK=32, 8 warps 4x2), cp.async 2-stage.
// Round-7 mainloop. QKV template: epilogue writes per-head split q/k/v arrays.
// ---------------------------------------------------------------------------
#define ASTR 40
#define G_A_HI 0
#define G_A_LO 10240
#define G_B_HI 20480
#define G_B_LO 25600
#define G_STG  30720
#define G_SMEM (2*G_STG)   // 61440

template<bool BIAS, bool RELU, bool QKV>
__global__ void __launch_bounds__(256)
hmma_gemm(const __half* __restrict__ Ahi, const __half* __restrict__ Alo,
          const __half* __restrict__ Bhi, const __half* __restrict__ Blo,
          const float* __restrict__ bias,
          __half* __restrict__ Chi, __half* __restrict__ Clo,
          int M, int N, int K) {
    extern __shared__ char smem[];
    uint32_t sb = smem_u32(smem);

    int t = threadIdx.x, wid = t >> 5, lane = t & 31;
    int warp_m = wid & 3;
    int warp_n = wid >> 2;
    int row0 = blockIdx.y * 128, col0 = blockIdx.x * 64;

    float acc[2][4][4];
    #pragma unroll
    for (int mt = 0; mt < 2; mt++)
        #pragma unroll
        for (int nt = 0; nt < 4; nt++)
            #pragma unroll
            for (int e = 0; e < 4; e++) acc[mt][nt][e] = 0.0f;

    int a_off  = (warp_m * 32 + (lane & 15)) * ASTR + (lane >> 4) * 8;
    int b_off4 = (warp_n * 32 + (lane & 7) + ((lane >> 4) << 3)) * ASTR
               + (((lane >> 3) & 1) << 3);

    auto load_stage = [&](int s, int kc) {
        uint32_t ub = sb + s * G_STG;
        #pragma unroll
        for (int l = 0; l < 2; l++) {
            int idx = t + l * 256;
            int r = idx >> 2, c4 = idx & 3;
            size_t gsrc = (size_t)(row0 + r) * K + kc + c4 * 8;
            cp16(ub + G_A_HI + r * 80 + c4 * 16, Ahi + gsrc);
            cp16(ub + G_A_LO + r * 80 + c4 * 16, Alo + gsrc);
        }
        {
            int r = t >> 2, c4 = t & 3;
            size_t gsrc = (size_t)(col0 + r) * K + kc + c4 * 8;
            cp16(ub + G_B_HI + r * 80 + c4 * 16, Bhi + gsrc);
            cp16(ub + G_B_LO + r * 80 + c4 * 16, Blo + gsrc);
        }
    };

    int nk = K >> 5;
    load_stage(0, 0);
    CP_COMMIT();

    for (int i = 0; i < nk; i++) {
        if (i + 1 < nk) { load_stage((i + 1) & 1, (i + 1) * 32); CP_COMMIT(); CP_WAIT(1); }
        else            { CP_WAIT(0); }
        __syncthreads();

        uint32_t stg = sb + (i & 1) * G_STG;
        #pragma unroll
        for (int s = 0; s < 3; s++) {
            uint32_t baseA = stg + ((s == 2) ? G_A_LO : G_A_HI);
            uint32_t baseB = stg + ((s == 1) ? G_B_LO : G_B_HI);
            #pragma unroll
            for (int kk = 0; kk < 32; kk += 16) {
                uint32_t afr[2][4];
                #pragma unroll
                for (int mt = 0; mt < 2; mt++)
                    ldmatrix_x4(afr[mt][0], afr[mt][1], afr[mt][2], afr[mt][3],
                                baseA + (uint32_t)(a_off + mt * 16 * ASTR + kk) * 2);
                uint32_t bfr[4][2];
                #pragma unroll
                for (int p = 0; p < 2; p++)
                    ldmatrix_x4(bfr[2*p][0], bfr[2*p][1], bfr[2*p+1][0], bfr[2*p+1][1],
                                baseB + (uint32_t)(b_off4 + p * 16 * ASTR + kk) * 2);
                #pragma unroll
                for (int mt = 0; mt < 2; mt++)
                    #pragma unroll
                    for (int nt = 0; nt < 4; nt++)
                        mma_16816(acc[mt][nt], afr[mt][0], afr[mt][1], afr[mt][2],
                                  afr[mt][3], bfr[nt][0], bfr[nt][1]);
            }
        }
        __syncthreads();
    }

    // epilogue
    int sel = 0;
    __half *dhi = Chi, *dlo = Clo;
    float qscale = 1.0f;
    if (QKV) {
        sel = col0 >> 8;
        dhi = (sel == 0) ? g_qhi : (sel == 1) ? g_khi : g_vhi;
        dlo = (sel == 0) ? g_qlo : (sel == 1) ? g_klo : g_vlo;
        if (sel == 0) qscale = LOG2E;
    }
    #pragma unroll
    for (int mt = 0; mt < 2; mt++) {
        int r_lo = row0 + warp_m * 32 + mt * 16 + (lane >> 2);
        #pragma unroll
        for (int nt = 0; nt < 4; nt++) {
            int c = col0 + warp_n * 32 + nt * 8 + (lane & 3) * 2;
            #pragma unroll
            for (int half = 0; half < 2; half++) {
                int r = r_lo + half * 8;
                float v0 = acc[mt][nt][half * 2 + 0];
                float v1 = acc[mt][nt][half * 2 + 1];
                if (BIAS) { v0 += bias[c]; v1 += bias[c + 1]; }
                if (RELU) { v0 = fmaxf(v0, 0.0f); v1 = fmaxf(v1, 0.0f); }
                if (QKV) {
                    if (sel == 0) { v0 *= qscale; v1 *= qscale; }
                    int hh = (c >> 5) & 7, kk = c & 31;
                    size_t dst = ((size_t)((r >> 11) * HH + hh) * SS + (r & 2047)) * DK + kk;
                    split_store2(v0, v1, dhi, dlo, dst);
                } else {
                    split_store2(v0, v1, dhi, dlo, (size_t)r * N + c);
                }
            }
        }
    }
}

// ---------------------------------------------------------------------------
// GEMM + residual + LayerNorm fused. Tile 32x256 (grid=128), 8 warps (2x4).
// Round-7 structure.
// ---------------------------------------------------------------------------
#define LG_A_HI 0
#define LG_A_LO 2560
#define LG_B_HI 5120
#define LG_B_LO 25600
#define LG_STG  46080
#define LG_SMEM (2*LG_STG)   // 92160 (epilogue fp32 buffer aliases stage 0)

template<bool BIAS, bool SPLITOUT>
__global__ void __launch_bounds__(256)
ln_gemm(const __half* __restrict__ Ahi, const __half* __restrict__ Alo,
        const __half* __restrict__ Bhi, const __half* __restrict__ Blo,
        const float* __restrict__ bias, const float* __restrict__ resp,
        float* __restrict__ xout, __half* __restrict__ Xhi,
        __half* __restrict__ Xlo, const float* __restrict__ gamma,
        const float* __restrict__ beta, int gi, int K) {
    extern __shared__ char smem[];
    uint32_t sb = smem_u32(smem);

    int t = threadIdx.x, wid = t >> 5, lane = t & 31;
    int warp_m = wid & 1;
    int warp_n = wid >> 1;
    int row0 = blockIdx.x * 32;

    float acc[8][4];
    #pragma unroll
    for (int nt = 0; nt < 8; nt++)
        #pragma unroll
        for (int e = 0; e < 4; e++) acc[nt][e] = 0.0f;

    int a_off   = (warp_m * 16 + (lane & 15)) * ASTR + (lane >> 4) * 8;
    int b_lane4 = ((lane & 7) + ((lane >> 4) << 3)) * ASTR + (((lane >> 3) & 1) << 3);

    auto load_stage = [&](int s, int kc) {
        uint32_t ub = sb + s * LG_STG;
        {
            int idx = t;
            int r = idx >> 3, which = (idx >> 2) & 1, c4 = idx & 3;
            size_t gsrc = (size_t)(row0 + r) * K + kc + c4 * 8;
            cp16(ub + (which ? LG_A_LO : LG_A_HI) + r * 80 + c4 * 16,
                 (which ? Alo : Ahi) + gsrc);
        }
        #pragma unroll
        for (int l = 0; l < 8; l++) {
            int idx = t + l * 256;
            int r = idx >> 3, which = (idx >> 2) & 1, c4 = idx & 3;
            size_t gsrc = (size_t)r * K + kc + c4 * 8;
            cp16(ub + (which ? LG_B_LO : LG_B_HI) + r * 80 + c4 * 16,
                 (which ? Blo : Bhi) + gsrc);
        }
    };

    int nk = K >> 5;
    load_stage(0, 0);
    CP_COMMIT();

    for (int i = 0; i < nk; i++) {
        if (i + 1 < nk) { load_stage((i + 1) & 1, (i + 1) * 32); CP_COMMIT(); CP_WAIT(1); }
        else            { CP_WAIT(0); }
        __syncthreads();

        uint32_t stg = sb + (i & 1) * LG_STG;
        #pragma unroll
        for (int s = 0; s < 3; s++) {
            uint32_t baseA = stg + ((s == 2) ? LG_A_LO : LG_A_HI);
            uint32_t baseB = stg + ((s == 1) ? LG_B_LO : LG_B_HI);
            #pragma unroll
            for (int kk = 0; kk < 32; kk += 16) {
                uint32_t a0, a1, a2, a3;
                ldmatrix_x4(a0, a1, a2, a3, baseA + (uint32_t)(a_off + kk) * 2);
                #pragma unroll
                for (int p = 0; p < 4; p++) {
                    uint32_t b0, b1, b2, b3;
                    ldmatrix_x4(b0, b1, b2, b3,
                        baseB + (uint32_t)(b_lane4 + (warp_n * 64 + p * 16) * ASTR + kk) * 2);
                    mma_16816(acc[2*p],   a0, a1, a2, a3, b0, b1);
                    mma_16816(acc[2*p+1], a0, a1, a2, a3, b2, b3);
                }
            }
        }
        __syncthreads();
    }

    // phase 1: bias + residual into fp32 smem rows
    float* fb = (float*)smem;
    #pragma unroll
    for (int nt = 0; nt < 8; nt++) {
        int col = warp_n * 64 + nt * 8 + (lane & 3) * 2;
        int rl  = warp_m * 16 + (lane >> 2);
        #pragma unroll
        for (int half = 0; half < 2; half++) {
            int r = rl + half * 8;
            size_t grb = (size_t)(row0 + r) * DD;
            float v0 = acc[nt][half * 2 + 0];
            float v1 = acc[nt][half * 2 + 1];
            if (BIAS) { v0 += bias[col]; v1 += bias[col + 1]; }
            v0 += resp[grb + col];
            v1 += resp[grb + col + 1];
            fb[r * DD + col] = v0;
            fb[r * DD + col + 1] = v1;
        }
    }
    __syncthreads();

    // phase 2: warp-per-row LayerNorm (each warp: 4 rows)
    float g = gamma[gi], bb = beta[gi];
    #pragma unroll
    for (int j = 0; j < 4; j++) {
        int r = wid * 4 + j;
        const float4* rp = (const float4*)(fb + r * DD);
        float4 v0 = rp[lane * 2], v1 = rp[lane * 2 + 1];

        float sum = v0.x + v0.y + v0.z + v0.w + v1.x + v1.y + v1.z + v1.w;
        #pragma unroll
        for (int off = 16; off > 0; off >>= 1)
            sum += __shfl_xor_sync(0xffffffffu, sum, off);
        float mean = sum * (1.0f / DD);

        float d0 = v0.x - mean, d1 = v0.y - mean, d2 = v0.z - mean, d3 = v0.w - mean;
        float d4 = v1.x - mean, d5 = v1.y - mean, d6 = v1.z - mean, d7 = v1.w - mean;
        float s2 = d0*d0 + d1*d1 + d2*d2 + d3*d3 + d4*d4 + d5*d5 + d6*d6 + d7*d7;
        #pragma unroll
        for (int off = 16; off > 0; off >>= 1)
            s2 += __shfl_xor_sync(0xffffffffu, s2, off);
        float rstd = rsqrtf(s2 * (1.0f / DD) + 1e-14f) * g;

        float o[8] = { d0*rstd + bb, d1*rstd + bb, d2*rstd + bb, d3*rstd + bb,
                       d4*rstd + bb, d5*rstd + bb, d6*rstd + bb, d7*rstd + bb };
        size_t gbase = (size_t)(row0 + r) * DD + lane * 8;
        *(float4*)(xout + gbase)     = make_float4(o[0], o[1], o[2], o[3]);
        *(float4*)(xout + gbase + 4) = make_float4(o[4], o[5], o[6], o[7]);
        if (SPLITOUT) {
            #pragma unroll
            for (int p = 0; p < 4; p++)
                split_store2(o[2*p], o[2*p+1], Xhi, Xlo, gbase + 2*p);
        }
    }
}

// ---------------------------------------------------------------------------
// HMMA flash attention: per-head contiguous q/k/v arrays, cp.async 2-stage,
// 4 warps (warp = 32 query rows). Round-7 mainloop + mask fast path.
// ---------------------------------------------------------------------------
#define ATT_Q_HI 0
#define ATT_Q_LO 10240
#define ATT_KV0  20480            // + stage*20480 + {Khi:0,Klo:5120,Vhi:10240,Vlo:15360}
#define ATT_KSTG 20480
#define ATT_M0   61440            // + stage*512 ; mask 64 floats, flag at +256
#define ATT_SMEM 62464

__global__ void __launch_bounds__(128) attention_hmma(const float* __restrict__ mask) {
    extern __shared__ char smem[];
    uint32_t sb = smem_u32(smem);

    int b = blockIdx.y >> 3, h = blockIdx.y & 7;
    int t = threadIdx.x, warp = t >> 5, lane = t & 31;
    int row0 = blockIdx.x * 128;
    size_t hb = (size_t)(b * HH + h) * SS * DK;   // per-head base

    auto load_kv = [&](int s, int t0) {
        uint32_t ub = sb + ATT_KV0 + s * ATT_KSTG;
        #pragma unroll
        for (int l = 0; l < 8; l++) {
            int idx = t + l * 128;               // 0..1023
            int which = idx >> 8;                // Khi, Klo, Vhi, Vlo
            int rem = idx & 255;
            int r = rem >> 2, c4 = rem & 3;
            const __half* src = (which == 0) ? g_khi : (which == 1) ? g_klo
                               : (which == 2) ? g_vhi : g_vlo;
            cp16(ub + which * 5120 + r * 80 + c4 * 16,
                 src + hb + (size_t)(t0 + r) * DK + c4 * 8);
        }
        if (t < 64)
            *(float*)(smem + ATT_M0 + s * 512 + t * 4) = mask[b * SS + t0 + t];
        if (t == 64)
            *(float*)(smem + ATT_M0 + s * 512 + 256) = g_mones[(b * SS + t0) >> 6];
    };

    load_kv(0, 0);
    CP_COMMIT();

    // Q (hi/lo) contiguous loads
    {
        #pragma unroll
        for (int l = 0; l < 8; l++) {
            int idx = t + l * 128;               // 0..1023
            int which = (idx >> 2) & 1, r = idx >> 3, c4 = idx & 3;
            const __half* src = which ? g_qlo : g_qhi;
            *(uint4*)(smem + (which ? ATT_Q_LO : ATT_Q_HI) + r * 80 + c4 * 16) =
                *(const uint4*)&src[hb + (size_t)(row0 + r) * DK + c4 * 8];
        }
    }
    __syncthreads();

    uint32_t qf[2][2][2][4];   // [hi/lo][mt][kstep][4]
    {
        int a_off = (warp * 32 + (lane & 15)) * ASTR + (lane >> 4) * 8;
        #pragma unroll
        for (int w2 = 0; w2 < 2; w2++) {
            uint32_t base = sb + (w2 ? ATT_Q_LO : ATT_Q_HI);
            #pragma unroll
            for (int mt = 0; mt < 2; mt++)
                #pragma unroll
                for (int ks = 0; ks < 2; ks++)
                    ldmatrix_x4(qf[w2][mt][ks][0], qf[w2][mt][ks][1],
                                qf[w2][mt][ks][2], qf[w2][mt][ks][3],
                                base + (uint32_t)(a_off + mt * 16 * ASTR + ks * 16) * 2);
        }
    }

    float m_run[2][2], l_run[2][2], oacc[2][4][4];
    #pragma unroll
    for (int mt = 0; mt < 2; mt++) {
        #pragma unroll
        for (int hf = 0; hf < 2; hf++) { m_run[mt][hf] = -1e30f; l_run[mt][hf] = 0.f; }
        #pragma unroll
        for (int nt = 0; nt < 4; nt++)
            #pragma unroll
            for (int e = 0; e < 4; e++) oacc[mt][nt][e] = 0.f;
    }

    const int ntiles = SS / 64;
    for (int i = 0; i < ntiles; i++) {
        if (i + 1 < ntiles) { load_kv((i + 1) & 1, (i + 1) * 64); CP_COMMIT(); CP_WAIT(1); }
        else                { CP_WAIT(0); }
        __syncthreads();

        uint32_t kvstg = sb + ATT_KV0 + (i & 1) * ATT_KSTG;
        const float* sM = (const float*)(smem + ATT_M0 + (i & 1) * 512);
        float ones = *(const float*)(smem + ATT_M0 + (i & 1) * 512 + 256);

        // S = Q K^T (3 split passes, round-7 form)
        float sc[2][8][4];
        #pragma unroll
        for (int mt = 0; mt < 2; mt++)
            #pragma unroll
            for (int nt = 0; nt < 8; nt++)
                #pragma unroll
                for (int e = 0; e < 4; e++) sc[mt][nt][e] = 0.f;
        {
            int b_off4 = ((lane & 7) + ((lane >> 4) << 3)) * ASTR
                       + (((lane >> 3) & 1) << 3);
            #pragma unroll
            for (int s = 0; s < 3; s++) {
                int wa = (s == 2) ? 1 : 0;
                uint32_t kbase = kvstg + ((s == 1) ? 5120 : 0);
                #pragma unroll
                for (int ks = 0; ks < 2; ks++)
                    #pragma unroll
                    for (int p = 0; p < 4; p++) {
                        uint32_t b0, b1, b2, b3;
                        ldmatrix_x4(b0, b1, b2, b3,
                            kbase + (uint32_t)(b_off4 + p * 16 * ASTR + ks * 16) * 2);
                        mma_16816(sc[0][2*p],   qf[wa][0][ks][0], qf[wa][0][ks][1],
                                  qf[wa][0][ks][2], qf[wa][0][ks][3], b0, b1);
                        mma_16816(sc[0][2*p+1], qf[wa][0][ks][0], qf[wa][0][ks][1],
                                  qf[wa][0][ks][2], qf[wa][0][ks][3], b2, b3);
                        mma_16816(sc[1][2*p],   qf[wa][1][ks][0], qf[wa][1][ks][1],
                                  qf[wa][1][ks][2], qf[wa][1][ks][3], b0, b1);
                        mma_16816(sc[1][2*p+1], qf[wa][1][ks][0], qf[wa][1][ks][1],
                                  qf[wa][1][ks][2], qf[wa][1][ks][3], b2, b3);
                    }
            }
        }

        // masking: skipped when chunk is all-ones (bit-exact: m=1 -> identity)
        if (ones == 0.0f) {
            #pragma unroll
            for (int nt = 0; nt < 8; nt++) {
                int c0 = nt * 8 + (lane & 3) * 2;
                float mvA = sM[c0], mvB = sM[c0 + 1];
                float cA = (1.f - mvA) * MV2L, cB = (1.f - mvB) * MV2L;
                #pragma unroll
                for (int mt = 0; mt < 2; mt++) {
                    sc[mt][nt][0] = fmaf(mvA, sc[mt][nt][0], cA);
                    sc[mt][nt][1] = fmaf(mvB, sc[mt][nt][1], cB);
                    sc[mt][nt][2] = fmaf(mvA, sc[mt][nt][2], cA);
                    sc[mt][nt][3] = fmaf(mvB, sc[mt][nt][3], cB);
                }
            }
        }

        float tmax[2][2] = {{-1e30f, -1e30f}, {-1e30f, -1e30f}};
        #pragma unroll
        for (int nt = 0; nt < 8; nt++)
            #pragma unroll
            for (int mt = 0; mt < 2; mt++) {
                tmax[mt][0] = fmaxf(tmax[mt][0], fmaxf(sc[mt][nt][0], sc[mt][nt][1]));
                tmax[mt][1] = fmaxf(tmax[mt][1], fmaxf(sc[mt][nt][2], sc[mt][nt][3]));
            }
        float corr[2][2];
        #pragma unroll
        for (int mt = 0; mt < 2; mt++)
            #pragma unroll
            for (int hf = 0; hf < 2; hf++) {
                float v = tmax[mt][hf];
                v = fmaxf(v, __shfl_xor_sync(0xffffffffu, v, 1));
                v = fmaxf(v, __shfl_xor_sync(0xffffffffu, v, 2));
                float mn = fmaxf(m_run[mt][hf], v);
                corr[mt][hf] = ex2f(m_run[mt][hf] - mn);
                m_run[mt][hf] = mn;
                l_run[mt][hf] *= corr[mt][hf];
            }
        #pragma unroll
        for (int mt = 0; mt < 2; mt++)
            #pragma unroll
            for (int nt = 0; nt < 4; nt++)
                #pragma unroll
                for (int e = 0; e < 4; e++)
                    oacc[mt][nt][e] *= corr[mt][e >> 1];

        uint32_t pf[2][4][4];
        #pragma unroll
        for (int mt = 0; mt < 2; mt++)
            #pragma unroll
            for (int nt = 0; nt < 8; nt++) {
                float p0 = ex2f(sc[mt][nt][0] - m_run[mt][0]);
                float p1 = ex2f(sc[mt][nt][1] - m_run[mt][0]);
                float p2 = ex2f(sc[mt][nt][2] - m_run[mt][1]);
                float p3 = ex2f(sc[mt][nt][3] - m_run[mt][1]);
                l_run[mt][0] += p0 + p1;
                l_run[mt][1] += p2 + p3;
                int kb = nt >> 1, hi2 = (nt & 1) * 2;
                pf[mt][kb][hi2 + 0] = pack_h2(p0, p1);
                pf[mt][kb][hi2 + 1] = pack_h2(p2, p3);
            }

        // O += P @ V (Vhi pass + Vlo pass), trans x4 loads
        #pragma unroll
        for (int s = 0; s < 2; s++) {
            uint32_t vbase = kvstg + (2 + s) * 5120;
            #pragma unroll
            for (int kb = 0; kb < 4; kb++) {
                uint32_t vrow = vbase +
                    (uint32_t)((kb * 16 + (lane & 15)) * ASTR + ((lane >> 4) << 3)) * 2;
                #pragma unroll
                for (int p = 0; p < 2; p++) {
                    uint32_t b0, b1, b2, b3;
                    ldmatrix_x4_trans(b0, b1, b2, b3, vrow + (uint32_t)(p * 16) * 2);
                    mma_16816(oacc[0][2*p],   pf[0][kb][0], pf[0][kb][1],
                              pf[0][kb][2], pf[0][kb][3], b0, b1);
                    mma_16816(oacc[0][2*p+1], pf[0][kb][0], pf[0][kb][1],
                              pf[0][kb][2], pf[0][kb][3], b2, b3);
                    mma_16816(oacc[1][2*p],   pf[1][kb][0], pf[1][kb][1],
                              pf[1][kb][2], pf[1][kb][3], b0, b1);
                    mma_16816(oacc[1][2*p+1], pf[1][kb][0], pf[1][kb][1],
                              pf[1][kb][2], pf[1][kb][3], b2, b3);
                }
            }
        }
        __syncthreads();
    }

    #pragma unroll
    for (int mt = 0; mt < 2; mt++)
        #pragma unroll
        for (int hf = 0; hf < 2; hf++) {
            float v = l_run[mt][hf];
            v += __shfl_xor_sync(0xffffffffu, v, 1);
            v += __shfl_xor_sync(0xffffffffu, v, 2);
            l_run[mt][hf] = 1.0f / v;
        }
    #pragma unroll
    for (int mt = 0; mt < 2; mt++)
        #pragma unroll
        for (int hf = 0; hf < 2; hf++) {
            int row = row0 + warp * 32 + mt * 16 + (lane >> 2) + hf * 8;
            size_t obase = (size_t)(b * SS + row) * DD + h * DV;
            float inv = l_run[mt][hf];
            #pragma unroll
            for (int nt = 0; nt < 4; nt++) {
                int col = nt * 8 + (lane & 3) * 2;
                split_store2(oacc[mt][nt][hf * 2 + 0] * inv,
                             oacc[mt][nt][hf * 2 + 1] * inv,
                             g_ohi, g_olo, obase + col);
            }
        }
}

// ---------------------------------------------------------------------------
// launch
// ---------------------------------------------------------------------------
extern "C" void kernel_launch(void* const* d_in, const int* in_sizes, int n_in,
                              void* d_out, int out_size) {
    const float* x     = (const float*)d_in[0];
    const float* mask  = (const float*)d_in[1];
    const float* Wq    = (const float*)d_in[2];
    const float* Wk    = (const float*)d_in[3];
    const float* Wv    = (const float*)d_in[4];
    const float* Wo    = (const float*)d_in[5];
    const float* W1    = (const float*)d_in[6];
    const float* b1    = (const float*)d_in[7];
    const float* W2    = (const float*)d_in[8];
    const float* b2    = (const float*)d_in[9];
    const float* gamma = (const float*)d_in[10];
    const float* beta  = (const float*)d_in[11];
    float* out = (float*)d_out;
    (void)in_sizes; (void)n_in; (void)out_size;

    float *p_x;
    __half *p_xhi, *p_xlo, *p_ohi, *p_olo, *p_hhi, *p_hlo;
    __half *p_wqkvhi, *p_wqkvlo, *p_wohi, *p_wolo, *p_w1hi, *p_w1lo, *p_w2hi, *p_w2lo;
    cudaGetSymbolAddress((void**)&p_x, g_x);
    cudaGetSymbolAddress((void**)&p_xhi, g_xhi);
    cudaGetSymbolAddress((void**)&p_xlo, g_xlo);
    cudaGetSymbolAddress((void**)&p_ohi, g_ohi);
    cudaGetSymbolAddress((void**)&p_olo, g_olo);
    cudaGetSymbolAddress((void**)&p_hhi, g_hhi);
    cudaGetSymbolAddress((void**)&p_hlo, g_hlo);
    cudaGetSymbolAddress((void**)&p_wqkvhi, g_wqkvhi);
    cudaGetSymbolAddress((void**)&p_wqkvlo, g_wqkvlo);
    cudaGetSymbolAddress((void**)&p_wohi, g_wohi);
    cudaGetSymbolAddress((void**)&p_wolo, g_wolo);
    cudaGetSymbolAddress((void**)&p_w1hi, g_w1hi);
    cudaGetSymbolAddress((void**)&p_w1lo, g_w1lo);
    cudaGetSymbolAddress((void**)&p_w2hi, g_w2hi);
    cudaGetSymbolAddress((void**)&p_w2lo, g_w2lo);

    cudaFuncSetAttribute(hmma_gemm<false,false,true>,
                         cudaFuncAttributeMaxDynamicSharedMemorySize, G_SMEM);
    cudaFuncSetAttribute(hmma_gemm<true,true,false>,
                         cudaFuncAttributeMaxDynamicSharedMemorySize, G_SMEM);
    cudaFuncSetAttribute(ln_gemm<false,true>,
                         cudaFuncAttributeMaxDynamicSharedMemorySize, LG_SMEM);
    cudaFuncSetAttribute(ln_gemm<true,true>,
                         cudaFuncAttributeMaxDynamicSharedMemorySize, LG_SMEM);
    cudaFuncSetAttribute(ln_gemm<true,false>,
                         cudaFuncAttributeMaxDynamicSharedMemorySize, LG_SMEM);
    cudaFuncSetAttribute(attention_hmma,
                         cudaFuncAttributeMaxDynamicSharedMemorySize, ATT_SMEM);

    // one prep launch: copy + split + all weight packs + mask flags
    prep_kernel<<<4096 + NLAYER*768 + 128 + 256 + 256 + 1, 256>>>(
        x, mask, Wq, Wk, Wv, Wo, W1, W2);

    for (int i = 0; i < NLAYER; i++) {
        // qkv = x @ Wqkv  -> per-head split q/k/v arrays (q scaled by log2e)
        hmma_gemm<false,false,true><<<dim3(QKV3/64, MTOT/128), 256, G_SMEM>>>(
            p_xhi, p_xlo,
            p_wqkvhi + (size_t)i * QKV3 * DD, p_wqkvlo + (size_t)i * QKV3 * DD,
            nullptr, nullptr, nullptr, MTOT, QKV3, DD);

        // flash attention -> o split fp16
        attention_hmma<<<dim3(SS/128, BB*HH), 128, ATT_SMEM>>>(mask);

        // x = LN(x + o @ Wo)
        ln_gemm<false,true><<<MTOT/32, 256, LG_SMEM>>>(
            p_ohi, p_olo,
            p_wohi + (size_t)i * DD * DD, p_wolo + (size_t)i * DD * DD,
            nullptr, p_x, p_x, p_xhi, p_xlo, gamma, beta, 2*i, DD);

        // h = relu(x @ W1 + b1) -> split fp16
        hmma_gemm<true,true,false><<<dim3(DFF/64, MTOT/128), 256, G_SMEM>>>(
            p_xhi, p_xlo,
            p_w1hi + (size_t)i * DFF * DD, p_w1lo + (size_t)i * DFF * DD,
            b1 + (size_t)i * DFF, p_hhi, p_hlo, MTOT, DFF, DD);

        // x = LN(x + h @ W2 + b2)  (final layer -> out)
        if (i == NLAYER - 1) {
            ln_gemm<true,false><<<MTOT/32, 256, LG_SMEM>>>(
                p_hhi, p_hlo,
                p_w2hi + (size_t)i * DD * DFF, p_w2lo + (size_t)i * DD * DFF,
                b2 + (size_t)i * DD, p_x, out, nullptr, nullptr,
                gamma, beta, 2*i+1, DFF);
        } else {
            ln_gemm<true,true><<<MTOT/32, 256, LG_SMEM>>>(
                p_hhi, p_hlo,
                p_w2hi + (size_t)i * DD * DFF, p_w2lo + (size_t)i * DD * DFF,
                b2 + (size_t)i * DD, p_x, p_x, p_xhi, p_xlo,
                gamma, beta, 2*i+1, DFF);
        }
    }
}